// round 4
// baseline (speedup 1.0000x reference)
#include <cuda_runtime.h>
#include <cuda_bf16.h>
#include <cstdint>

// Problem constants
#define Bb 8
#define Ss 2048
#define Dd 512
#define Qq 8
#define Kk 1024
#define Mm (Bb * Ss)   // 16384 tokens

// Scratch (no cudaMalloc allowed)
__device__ float          g_residual[Mm * Dd];   // 32 MB fp32 residual
__device__ __nv_bfloat16  g_res16[Mm * Dd];      // 16 MB bf16 residual
__device__ __nv_bfloat16  g_cb16[Qq * Kk * Dd];  //  8 MB bf16 codebooks
__device__ float          g_c2[Qq * Kk];
__device__ float          g_loss[Qq];

// smem layout (dynamic, byte offsets)
#define SM_A    0        // 8 k-chunks x 16384 B = 131072
#define SM_B    131072   // 2 bufs x 16384 B = 32768
#define SM_C2   163840   // 1024 f32 = 4096
#define SM_RMIN 167936   // 128 u32
#define SM_CNT  168448   // 128 i32
#define SM_CAND 168960   // 128 x 32 u16 = 8192
#define SM_TOTAL 177152
#define CAND_CAP 30
#define MARGIN 12.0f

// ---------------------------------------------------------------------------
// helpers
// ---------------------------------------------------------------------------
__device__ __forceinline__ uint32_t smem_u32(const void* p) {
    uint32_t a;
    asm("{ .reg .u64 t; cvta.to.shared.u64 t, %1; cvt.u32.u64 %0, t; }"
        : "=r"(a) : "l"(p));
    return a;
}
__device__ __forceinline__ void cp16(uint32_t sa, const void* g) {
    asm volatile("cp.async.cg.shared.global [%0], [%1], 16;"
                 :: "r"(sa), "l"(g) : "memory");
}
__device__ __forceinline__ void cp_commit() {
    asm volatile("cp.async.commit_group;" ::: "memory");
}
__device__ __forceinline__ void cp_wait1() {
    asm volatile("cp.async.wait_group 1;" ::: "memory");
}
__device__ __forceinline__ void cp_wait0() {
    asm volatile("cp.async.wait_group 0;" ::: "memory");
}
__device__ __forceinline__ void ldsm4(uint32_t* r, uint32_t addr) {
    asm volatile("ldmatrix.sync.aligned.m8n8.x4.shared.b16 {%0,%1,%2,%3}, [%4];"
                 : "=r"(r[0]), "=r"(r[1]), "=r"(r[2]), "=r"(r[3])
                 : "r"(addr));
}
__device__ __forceinline__ void mma_bf16(float* c, const uint32_t* a,
                                         uint32_t b0, uint32_t b1) {
    asm volatile(
        "mma.sync.aligned.m16n8k16.row.col.f32.bf16.bf16.f32 "
        "{%0,%1,%2,%3}, {%4,%5,%6,%7}, {%8,%9}, {%0,%1,%2,%3};"
        : "+f"(c[0]), "+f"(c[1]), "+f"(c[2]), "+f"(c[3])
        : "r"(a[0]), "r"(a[1]), "r"(a[2]), "r"(a[3]), "r"(b0), "r"(b1));
}
// order-preserving float <-> uint for atomicMin
__device__ __forceinline__ uint32_t ordkey(float f) {
    uint32_t u = __float_as_uint(f);
    return (u & 0x80000000u) ? ~u : (u | 0x80000000u);
}
__device__ __forceinline__ float orddec(uint32_t k) {
    return (k & 0x80000000u) ? __uint_as_float(k ^ 0x80000000u)
                             : __uint_as_float(~k);
}

// ---------------------------------------------------------------------------
// init: residual=x (fp32), res16=bf16(x), out=0
// ---------------------------------------------------------------------------
__global__ void init_kernel(const float4* __restrict__ x,
                            float4* __restrict__ residual,
                            __nv_bfloat162* __restrict__ res16,
                            float4* __restrict__ outq, int n4)
{
    int i = blockIdx.x * 256 + threadIdx.x;
    if (i < n4) {
        float4 v = x[i];
        residual[i] = v;
        res16[2 * i]     = __floats2bfloat162_rn(v.x, v.y);
        res16[2 * i + 1] = __floats2bfloat162_rn(v.z, v.w);
        outq[i] = make_float4(0.f, 0.f, 0.f, 0.f);
    }
}

// fp32 -> bf16 codebook convert
__global__ void conv_kernel(const float4* __restrict__ in,
                            __nv_bfloat162* __restrict__ out, int n4)
{
    int i = blockIdx.x * 256 + threadIdx.x;
    if (i < n4) {
        float4 v = in[i];
        out[2 * i]     = __floats2bfloat162_rn(v.x, v.y);
        out[2 * i + 1] = __floats2bfloat162_rn(v.z, v.w);
    }
}

// ---------------------------------------------------------------------------
// c2[q][k] = ||codebook[q][k]||^2  — one warp per row (fp32 exact)
// ---------------------------------------------------------------------------
__global__ void c2_kernel(const float* __restrict__ codebooks, float* __restrict__ c2)
{
    int row  = blockIdx.x * 8 + (threadIdx.x >> 5);
    int lane = threadIdx.x & 31;
    const float4* p = (const float4*)(codebooks + (size_t)row * Dd);
    float s = 0.0f;
    #pragma unroll 4
    for (int i = lane; i < Dd / 4; i += 32) {
        float4 v = p[i];
        s += v.x * v.x + v.y * v.y + v.z * v.z + v.w * v.w;
    }
    #pragma unroll
    for (int off = 16; off; off >>= 1) s += __shfl_down_sync(0xffffffffu, s, off);
    if (lane == 0) c2[row] = s;
}

// ---------------------------------------------------------------------------
// One full VQ stage per launch.
// Grid 128 CTAs x 256 threads. CTA owns tokens [m0, m0+128) x all 1024 codes.
// A resident in smem; B double-buffered; epilogue -> running argmin + candidate
// lists; tail: exact fp32 rescore + fused residual/out/loss/index update.
// ---------------------------------------------------------------------------
__global__ __launch_bounds__(256, 1)
void vq_stage_kernel(const __nv_bfloat16* __restrict__ A16,
                     const __nv_bfloat16* __restrict__ B16,
                     float* __restrict__ R,
                     __nv_bfloat16* __restrict__ R16w,
                     const float* __restrict__ C,
                     const float* __restrict__ c2,
                     float* __restrict__ outq,
                     float* __restrict__ out_idx,
                     float* __restrict__ loss,
                     int qstage)
{
    extern __shared__ char sm[];
    const uint32_t smb = smem_u32(sm);

    const int tid  = threadIdx.x;
    const int lane = tid & 31;
    const int warp = tid >> 5;
    const int m0   = blockIdx.x * 128;
    const int wm   = (warp & 3) * 32;
    const int wn   = (warp >> 2) * 64;

    float*     c2s  = (float*)(sm + SM_C2);
    uint32_t*  rmin = (uint32_t*)(sm + SM_RMIN);
    int*       ccnt = (int*)(sm + SM_CNT);
    uint16_t*  cand = (uint16_t*)(sm + SM_CAND);

    const char* gA = (const char*)(A16 + (size_t)m0 * Dd);
    const char* gB = (const char*)B16;

    // ---- prologue: A (all 8 chunks) + B chunk 0, one commit group ----
    #pragma unroll
    for (int i = 0; i < 32; ++i) {
        int u = tid + 256 * i;
        int kt = u >> 10, rem = u & 1023;
        int row = rem >> 3, ch = rem & 7;
        cp16(smb + SM_A + kt * 16384 + row * 128 + ((ch ^ (row & 7)) * 16),
             gA + (size_t)row * 1024 + kt * 128 + ch * 16);
    }
    #pragma unroll
    for (int i = 0; i < 4; ++i) {
        int u = tid + 256 * i;
        int row = u >> 3, ch = u & 7;
        cp16(smb + SM_B + row * 128 + ((ch ^ (row & 7)) * 16),
             gB + (size_t)row * 1024 + ch * 16);
    }
    cp_commit();

    ((float4*)c2s)[tid] = ((const float4*)c2)[tid];   // 1024 floats / 256 thr
    if (tid < 128) { rmin[tid] = 0xFFFFFFFFu; ccnt[tid] = 0; }

    const int g  = lane >> 2;
    const int t4 = lane & 3;

    // ---- main loop over 8 n-tiles ----
    for (int nt = 0; nt < 8; ++nt) {
        float acc[2][8][4];
        #pragma unroll
        for (int mi = 0; mi < 2; ++mi)
            #pragma unroll
            for (int ni = 0; ni < 8; ++ni)
                #pragma unroll
                for (int j = 0; j < 4; ++j) acc[mi][ni][j] = 0.0f;

        for (int kt = 0; kt < 8; ++kt) {
            const int cidx = nt * 8 + kt;
            if (cidx < 63) {
                const int nc = cidx + 1;
                const int nnt = nc >> 3, nkt = nc & 7, nbuf = nc & 1;
                #pragma unroll
                for (int i = 0; i < 4; ++i) {
                    int u = tid + 256 * i;
                    int row = u >> 3, ch = u & 7;
                    cp16(smb + SM_B + nbuf * 16384 + row * 128 + ((ch ^ (row & 7)) * 16),
                         gB + (size_t)(nnt * 128 + row) * 1024 + nkt * 128 + ch * 16);
                }
                cp_commit();
                cp_wait1();
            } else {
                cp_wait0();
            }
            __syncthreads();

            const int buf = cidx & 1;
            #pragma unroll
            for (int s = 0; s < 4; ++s) {
                uint32_t a[2][4], b[4][4];
                const int ch = s * 2 + (lane >> 4);
                #pragma unroll
                for (int mi = 0; mi < 2; ++mi) {
                    int row = wm + mi * 16 + (lane & 15);
                    ldsm4(a[mi], smb + SM_A + kt * 16384 + row * 128 +
                                 ((ch ^ (row & 7)) * 16));
                }
                #pragma unroll
                for (int nj = 0; nj < 4; ++nj) {
                    int row = wn + nj * 16 + (lane & 15);
                    ldsm4(b[nj], smb + SM_B + buf * 16384 + row * 128 +
                                 ((ch ^ (row & 7)) * 16));
                }
                #pragma unroll
                for (int mi = 0; mi < 2; ++mi)
                    #pragma unroll
                    for (int ni = 0; ni < 8; ++ni)
                        mma_bf16(acc[mi][ni], a[mi],
                                 b[ni >> 1][ni & 1], b[ni >> 1][(ni & 1) + 2]);
            }
            __syncthreads();
        }

        // ---- epilogue: running min + candidate append ----
        float rm[4] = {3.4e38f, 3.4e38f, 3.4e38f, 3.4e38f};   // [mi*2 + half]
        #pragma unroll
        for (int mi = 0; mi < 2; ++mi)
            #pragma unroll
            for (int ni = 0; ni < 8; ++ni)
                #pragma unroll
                for (int j = 0; j < 4; ++j) {
                    int ng = nt * 128 + wn + ni * 8 + 2 * t4 + (j & 1);
                    float d = fmaf(-2.0f, acc[mi][ni][j], c2s[ng]);
                    int h = mi * 2 + (j >> 1);
                    rm[h] = fminf(rm[h], d);
                }
        #pragma unroll
        for (int h = 0; h < 4; ++h) {
            int row = wm + (h >> 1) * 16 + g + (h & 1) * 8;
            atomicMin(&rmin[row], ordkey(rm[h]));
        }
        __syncthreads();

        float thr[4];
        #pragma unroll
        for (int h = 0; h < 4; ++h) {
            int row = wm + (h >> 1) * 16 + g + (h & 1) * 8;
            thr[h] = orddec(rmin[row]) + MARGIN;
        }
        #pragma unroll
        for (int mi = 0; mi < 2; ++mi)
            #pragma unroll
            for (int ni = 0; ni < 8; ++ni)
                #pragma unroll
                for (int j = 0; j < 4; ++j) {
                    int ng = nt * 128 + wn + ni * 8 + 2 * t4 + (j & 1);
                    float d = fmaf(-2.0f, acc[mi][ni][j], c2s[ng]);
                    int h = mi * 2 + (j >> 1);
                    if (d <= thr[h]) {
                        int row = wm + mi * 16 + g + (j >> 1) * 8;
                        int pos = atomicAdd(&ccnt[row], 1);
                        if (pos < CAND_CAP) cand[row * 32 + pos] = (uint16_t)ng;
                    }
                }
        __syncthreads();
    }

    // ---- exact rescore + fused update: warp per token, 16 tokens/warp ----
    float lsum = 0.0f;
    const int t0 = warp * 16;
    for (int tt = 0; tt < 16; ++tt) {
        const int tl = t0 + tt;
        const int token = m0 + tl;
        const float4* rrp = (const float4*)(R + (size_t)token * Dd);
        float4 rr[4];
        #pragma unroll
        for (int j = 0; j < 4; ++j) rr[j] = rrp[lane + 32 * j];

        const int cnt = ccnt[tl];
        float bd = 3.4e38f;
        int   bn = 1 << 30;

        if (cnt <= CAND_CAP) {
            for (int i = 0; i < cnt; ++i) {
                const int n = cand[tl * 32 + i];
                const float4* cp = (const float4*)(C + (size_t)n * Dd);
                float s = 0.0f;
                #pragma unroll
                for (int j = 0; j < 4; ++j) {
                    float4 b = cp[lane + 32 * j];
                    s += rr[j].x * b.x + rr[j].y * b.y +
                         rr[j].z * b.z + rr[j].w * b.w;
                }
                #pragma unroll
                for (int o = 16; o; o >>= 1) s += __shfl_xor_sync(~0u, s, o);
                float d = fmaf(-2.0f, s, c2s[n]);
                if (d < bd || (d == bd && n < bn)) { bd = d; bn = n; }
            }
        } else {
            // overflow fallback (effectively never): exact scan over all codes
            for (int n = 0; n < Kk; ++n) {
                const float4* cp = (const float4*)(C + (size_t)n * Dd);
                float s = 0.0f;
                #pragma unroll
                for (int j = 0; j < 4; ++j) {
                    float4 b = cp[lane + 32 * j];
                    s += rr[j].x * b.x + rr[j].y * b.y +
                         rr[j].z * b.z + rr[j].w * b.w;
                }
                #pragma unroll
                for (int o = 16; o; o >>= 1) s += __shfl_xor_sync(~0u, s, o);
                float d = fmaf(-2.0f, s, c2s[n]);
                if (d < bd || (d == bd && n < bn)) { bd = d; bn = n; }
            }
        }

        // fused update
        const float4* cp = (const float4*)(C + (size_t)bn * Dd);
        float4* rp = (float4*)(R + (size_t)token * Dd);
        float4* op = (float4*)(outq + (size_t)token * Dd);
        __nv_bfloat162* r16p = (__nv_bfloat162*)(R16w + (size_t)token * Dd);
        #pragma unroll
        for (int j = 0; j < 4; ++j) {
            float4 cv = cp[lane + 32 * j];
            float4 nr = make_float4(rr[j].x - cv.x, rr[j].y - cv.y,
                                    rr[j].z - cv.z, rr[j].w - cv.w);
            rp[lane + 32 * j] = nr;
            r16p[2 * (lane + 32 * j)]     = __floats2bfloat162_rn(nr.x, nr.y);
            r16p[2 * (lane + 32 * j) + 1] = __floats2bfloat162_rn(nr.z, nr.w);
            float4 ov = op[lane + 32 * j];
            op[lane + 32 * j] = make_float4(ov.x + cv.x, ov.y + cv.y,
                                            ov.z + cv.z, ov.w + cv.w);
            lsum += nr.x * nr.x + nr.y * nr.y + nr.z * nr.z + nr.w * nr.w;
        }
        if (lane == 0) out_idx[(size_t)token * Qq + qstage] = (float)bn;
    }
    #pragma unroll
    for (int o = 16; o; o >>= 1) lsum += __shfl_xor_sync(~0u, lsum, o);
    if (lane == 0) atomicAdd(loss, lsum);
}

// ---------------------------------------------------------------------------
// Tail outputs: all_expired (zeros) then all_losses (mean over B*S*D)
// ---------------------------------------------------------------------------
__global__ void finalize_kernel(float* __restrict__ out, const float* __restrict__ loss)
{
    const size_t base = (size_t)Mm * Dd + (size_t)Mm * Qq;
    int t = threadIdx.x;
    if (t < Qq)
        out[base + t] = 0.0f;
    else if (t < 2 * Qq)
        out[base + Qq + (t - Qq)] = loss[t - Qq] * (1.0f / ((float)Mm * (float)Dd));
}

// ---------------------------------------------------------------------------
extern "C" void kernel_launch(void* const* d_in, const int* in_sizes, int n_in,
                              void* d_out, int out_size)
{
    const float* x  = (const float*)d_in[0];   // [B,S,D] f32
    const float* cb = (const float*)d_in[1];   // [Q,K,D] f32
    float* out = (float*)d_out;

    float* residual;         cudaGetSymbolAddress((void**)&residual, g_residual);
    __nv_bfloat16* res16;    cudaGetSymbolAddress((void**)&res16,    g_res16);
    __nv_bfloat16* cb16;     cudaGetSymbolAddress((void**)&cb16,     g_cb16);
    float* c2;               cudaGetSymbolAddress((void**)&c2,       g_c2);
    float* loss;             cudaGetSymbolAddress((void**)&loss,     g_loss);

    cudaFuncSetAttribute(vq_stage_kernel,
                         cudaFuncAttributeMaxDynamicSharedMemorySize, SM_TOTAL);

    cudaMemsetAsync(loss, 0, Qq * sizeof(float));

    init_kernel<<<Mm * Dd / 4 / 256, 256>>>((const float4*)x, (float4*)residual,
                                            (__nv_bfloat162*)res16, (float4*)out,
                                            Mm * Dd / 4);
    conv_kernel<<<(Qq * Kk * Dd / 4 + 255) / 256, 256>>>((const float4*)cb,
                                                         (__nv_bfloat162*)cb16,
                                                         Qq * Kk * Dd / 4);
    c2_kernel<<<Qq * Kk / 8, 256>>>(cb, c2);

    for (int q = 0; q < Qq; ++q) {
        vq_stage_kernel<<<128, 256, SM_TOTAL>>>(
            res16, cb16 + (size_t)q * Kk * Dd,
            residual, res16,
            cb + (size_t)q * Kk * Dd, c2 + q * Kk,
            out, out + (size_t)Mm * Dd, loss + q, q);
    }

    finalize_kernel<<<1, 2 * Qq>>>(out, loss);
}